// round 16
// baseline (speedup 1.0000x reference)
#include <cuda_runtime.h>
#include <cuda_bf16.h>
#include <math.h>
#include <cstdint>

#define BB   4
#define SS   2048
#define DD   1024
#define HH   16
#define HD   64
#define DFF  4096
#define ROWS (BB*SS)   // 8192
#define QKVS 3072      // packed q|k|v row stride

// ---------------- scratch (allocation-free: __device__ globals) ----------------
__device__ float g_x2 [ROWS*(size_t)DD];
__device__ __nv_bfloat16 g_ahi[ROWS*(size_t)DFF];   // activation split A (hi)
__device__ __nv_bfloat16 g_alo[ROWS*(size_t)DFF];   // activation split A (lo)
__device__ __nv_bfloat16 g_bhi[ROWS*(size_t)DFF];   // activation split B (hi): qkv / ffn
__device__ __nv_bfloat16 g_blo[ROWS*(size_t)DFF];   // activation split B (lo)
__device__ __nv_bfloat16 g_whi[DD*(size_t)DFF];     // weight^T split (hi)  [N,K]
__device__ __nv_bfloat16 g_wlo[DD*(size_t)DFF];     // weight^T split (lo)  [N,K]

__device__ __forceinline__ uint32_t smem_to_u32(const void* p) {
    uint32_t a;
    asm("{ .reg .u64 t; cvta.to.shared.u64 t, %1; cvt.u32.u64 %0, t; }" : "=r"(a) : "l"(p));
    return a;
}
#define CP_ASYNC16(sa, gp) \
    asm volatile("cp.async.cg.shared.global [%0], [%1], 16;" :: "r"(sa), "l"(gp))
#define CP_COMMIT() asm volatile("cp.async.commit_group;" ::: "memory")
#define CP_WAIT(n)  asm volatile("cp.async.wait_group %0;" :: "n"(n) : "memory")

__device__ __forceinline__ void ldmx4(uint32_t* r, uint32_t addr) {
    asm volatile("ldmatrix.sync.aligned.m8n8.x4.shared.b16 {%0,%1,%2,%3}, [%4];"
        : "=r"(r[0]), "=r"(r[1]), "=r"(r[2]), "=r"(r[3]) : "r"(addr));
}
__device__ __forceinline__ void ldmx2(uint32_t* r, uint32_t addr) {
    asm volatile("ldmatrix.sync.aligned.m8n8.x2.shared.b16 {%0,%1}, [%2];"
        : "=r"(r[0]), "=r"(r[1]) : "r"(addr));
}
__device__ __forceinline__ void ldmx2t(uint32_t* r, uint32_t addr) {
    asm volatile("ldmatrix.sync.aligned.m8n8.x2.trans.shared.b16 {%0,%1}, [%2];"
        : "=r"(r[0]), "=r"(r[1]) : "r"(addr));
}
__device__ __forceinline__ void mma16816(float* c, const uint32_t* a, const uint32_t* b) {
    asm volatile("mma.sync.aligned.m16n8k16.row.col.f32.bf16.bf16.f32 "
        "{%0,%1,%2,%3}, {%4,%5,%6,%7}, {%8,%9}, {%0,%1,%2,%3};"
        : "+f"(c[0]), "+f"(c[1]), "+f"(c[2]), "+f"(c[3])
        : "r"(a[0]), "r"(a[1]), "r"(a[2]), "r"(a[3]), "r"(b[0]), "r"(b[1]));
}

__device__ __forceinline__ void split2(float a, float b, uint32_t& hi, uint32_t& lo) {
    __nv_bfloat16 ha = __float2bfloat16(a), hb = __float2bfloat16(b);
    __nv_bfloat16 la = __float2bfloat16(a - __bfloat162float(ha));
    __nv_bfloat16 lb = __float2bfloat16(b - __bfloat162float(hb));
    __nv_bfloat162 H = __halves2bfloat162(ha, hb), L = __halves2bfloat162(la, lb);
    hi = *(uint32_t*)&H; lo = *(uint32_t*)&L;
}
__device__ __forceinline__ void store_split2(__nv_bfloat16* hi, __nv_bfloat16* lo,
                                             size_t off, float a, float b) {
    __nv_bfloat16 ha = __float2bfloat16(a), hb = __float2bfloat16(b);
    __nv_bfloat16 la = __float2bfloat16(a - __bfloat162float(ha));
    __nv_bfloat16 lb = __float2bfloat16(b - __bfloat162float(hb));
    *(__nv_bfloat162*)(hi + off) = __halves2bfloat162(ha, hb);
    *(__nv_bfloat162*)(lo + off) = __halves2bfloat162(la, lb);
}

// ---------------- fused LayerNorm + bf16 hi/lo split ----------------
__global__ void __launch_bounds__(256) ln_split(const float* __restrict__ x,
                                                const float* __restrict__ sc,
                                                const float* __restrict__ sh,
                                                __nv_bfloat16* __restrict__ hi,
                                                __nv_bfloat16* __restrict__ lo)
{
    const int row = blockIdx.x;
    const float* xr = x + (size_t)row * DD;
    const int c = threadIdx.x * 4;
    float4 v = *(const float4*)(xr + c);
    float s  = v.x + v.y + v.z + v.w;
    float q  = v.x*v.x + v.y*v.y + v.z*v.z + v.w*v.w;
    #pragma unroll
    for (int o = 16; o; o >>= 1) {
        s += __shfl_xor_sync(0xffffffffu, s, o);
        q += __shfl_xor_sync(0xffffffffu, q, o);
    }
    __shared__ float ssum[8], sq[8];
    const int w = threadIdx.x >> 5, ln = threadIdx.x & 31;
    if (ln == 0) { ssum[w] = s; sq[w] = q; }
    __syncthreads();
    float tot = 0.f, totq = 0.f;
    #pragma unroll
    for (int i = 0; i < 8; i++) { tot += ssum[i]; totq += sq[i]; }
    const float mean = tot * (1.0f / DD);
    const float var  = totq * (1.0f / DD) - mean * mean;
    const float inv  = rsqrtf(var + 1e-8f);
    float4 scv = *(const float4*)(sc + c);
    float4 shv = *(const float4*)(sh + c);
    float o0 = scv.x * (v.x - mean) * inv + shv.x;
    float o1 = scv.y * (v.y - mean) * inv + shv.y;
    float o2 = scv.z * (v.z - mean) * inv + shv.z;
    float o3 = scv.w * (v.w - mean) * inv + shv.w;
    const size_t off = (size_t)row * DD + c;
    store_split2(hi, lo, off,     o0, o1);
    store_split2(hi, lo, off + 2, o2, o3);
}

__device__ __forceinline__ float gelu_f(float x)
{
    float x3 = x * x * x;
    float t  = tanhf(0.7978845608028654f * (x + 0.044715f * x3));
    return 0.5f * x * (1.0f + t);
}

// ---------------- split + transpose weights: W[K,N] fp32 -> hiT/loT [N,K] bf16 --------
__global__ void __launch_bounds__(256) wt_split_T(const float* __restrict__ W,
                                                  __nv_bfloat16* __restrict__ hiT,
                                                  __nv_bfloat16* __restrict__ loT,
                                                  int K, int N)
{
    __shared__ float t[32][33];
    const int n0 = blockIdx.x * 32, k0 = blockIdx.y * 32;
    const int tx = threadIdx.x & 31, ty = threadIdx.x >> 5;
    #pragma unroll
    for (int i = ty; i < 32; i += 8)
        t[i][tx] = W[(size_t)(k0 + i) * N + n0 + tx];
    __syncthreads();
    #pragma unroll
    for (int i = ty; i < 32; i += 8) {
        float v = t[tx][i];
        __nv_bfloat16 h = __float2bfloat16(v);
        __nv_bfloat16 l = __float2bfloat16(v - __bfloat162float(h));
        const size_t o = (size_t)(n0 + i) * K + k0 + tx;
        hiT[o] = h;  loT[o] = l;
    }
}

// ================= warp-MMA GEMM =================
// MODE 0: plain -> split bf16 out   MODE 1: +bias+residual -> fp32   MODE 2: +bias,gelu -> split
#define PB   40
#define TILE_B (128 * PB * 2)
#define STAGE_B (4 * TILE_B)
#define MM_SMEM (2 * STAGE_B)

template<int MODE>
__global__ void __launch_bounds__(256, 2) mm_gemm(
    const __nv_bfloat16* __restrict__ Ahi, const __nv_bfloat16* __restrict__ Alo,
    const __nv_bfloat16* __restrict__ BhiT, const __nv_bfloat16* __restrict__ BloT,
    const float* __restrict__ bias, const float* __restrict__ res,
    float* __restrict__ C, __nv_bfloat16* __restrict__ Ohi, __nv_bfloat16* __restrict__ Olo,
    int N, int K)
{
    extern __shared__ char smem[];
    const int tid  = threadIdx.x;
    const int lane = tid & 31, wid = tid >> 5;
    const int m0 = blockIdx.y * 128, n0 = blockIdx.x * 128;
    const int wm = (wid & 3) * 32, wn = (wid >> 2) * 64;

    const uint32_t sb = smem_to_u32(smem);
    const int r0g = tid >> 2,         c0g = (tid & 3) * 8;
    const int r1g = (tid + 256) >> 2, c1g = ((tid + 256) & 3) * 8;
    const uint32_t s0 = (uint32_t)(r0g * PB + c0g) * 2;
    const uint32_t s1 = (uint32_t)(r1g * PB + c1g) * 2;

    float acc[2][8][4];
    #pragma unroll
    for (int i = 0; i < 2; i++)
        #pragma unroll
        for (int j = 0; j < 8; j++)
            #pragma unroll
            for (int e = 0; e < 4; e++) acc[i][j][e] = 0.f;

    const int nch = K >> 5;

    auto load_chunk = [&](int c, int buf) {
        const int k0 = c << 5;
        const uint32_t st = sb + buf * STAGE_B;
        const __nv_bfloat16* aH = Ahi  + (size_t)m0 * K + k0;
        const __nv_bfloat16* aL = Alo  + (size_t)m0 * K + k0;
        const __nv_bfloat16* bH = BhiT + (size_t)n0 * K + k0;
        const __nv_bfloat16* bL = BloT + (size_t)n0 * K + k0;
        const size_t g0 = (size_t)r0g * K + c0g;
        const size_t g1 = (size_t)r1g * K + c1g;
        CP_ASYNC16(st + 0*TILE_B + s0, aH + g0);
        CP_ASYNC16(st + 0*TILE_B + s1, aH + g1);
        CP_ASYNC16(st + 1*TILE_B + s0, aL + g0);
        CP_ASYNC16(st + 1*TILE_B + s1, aL + g1);
        CP_ASYNC16(st + 2*TILE_B + s0, bH + g0);
        CP_ASYNC16(st + 2*TILE_B + s1, bH + g1);
        CP_ASYNC16(st + 3*TILE_B + s0, bL + g0);
        CP_ASYNC16(st + 3*TILE_B + s1, bL + g1);
    };

    load_chunk(0, 0);
    CP_COMMIT();

    const uint32_t aoff = (uint32_t)((wm + (lane & 15)) * PB + (lane >> 4) * 8) * 2;
    const uint32_t boff = (uint32_t)((wn + (lane & 7)) * PB + ((lane >> 3) & 1) * 8) * 2;

    for (int c = 0; c < nch; ++c) {
        const int buf = c & 1;
        const bool pre = (c + 1 < nch);
        if (pre) { load_chunk(c + 1, buf ^ 1); CP_COMMIT(); CP_WAIT(1); }
        else CP_WAIT(0);
        __syncthreads();

        const uint32_t stA_h = sb + buf * STAGE_B;
        const uint32_t stA_l = stA_h + TILE_B;
        const uint32_t stB_h = stA_h + 2 * TILE_B;
        const uint32_t stB_l = stA_h + 3 * TILE_B;

        #pragma unroll
        for (int ks = 0; ks < 2; ks++) {
            const uint32_t kso = (uint32_t)(ks * 16) * 2;
            uint32_t aH[2][4], aL[2][4];
            #pragma unroll
            for (int i = 0; i < 2; i++) {
                ldmx4(aH[i], stA_h + aoff + kso + (uint32_t)(i * 16 * PB) * 2);
                ldmx4(aL[i], stA_l + aoff + kso + (uint32_t)(i * 16 * PB) * 2);
            }
            #pragma unroll
            for (int jh = 0; jh < 2; jh++) {
                uint32_t bh[4][2], bl[4][2];
                #pragma unroll
                for (int j = 0; j < 4; j++) {
                    const uint32_t jo = (uint32_t)((jh * 4 + j) * 8 * PB) * 2;
                    ldmx2(bh[j], stB_h + boff + kso + jo);
                    ldmx2(bl[j], stB_l + boff + kso + jo);
                }
                #pragma unroll
                for (int i = 0; i < 2; i++)
                    #pragma unroll
                    for (int j = 0; j < 4; j++) {
                        float* a = acc[i][jh * 4 + j];
                        mma16816(a, aH[i], bh[j]);
                        mma16816(a, aH[i], bl[j]);
                        mma16816(a, aL[i], bh[j]);
                    }
            }
        }
        __syncthreads();
    }

    #pragma unroll
    for (int i = 0; i < 2; i++) {
        const int r = m0 + wm + i * 16 + (lane >> 2);
        #pragma unroll
        for (int j = 0; j < 8; j++) {
            const int col = n0 + wn + j * 8 + (lane & 3) * 2;
            float v0 = acc[i][j][0], v1 = acc[i][j][1];
            float v2 = acc[i][j][2], v3 = acc[i][j][3];
            if (MODE >= 1) {
                float2 bb = *(const float2*)(bias + col);
                v0 += bb.x; v1 += bb.y; v2 += bb.x; v3 += bb.y;
            }
            if (MODE == 2) { v0 = gelu_f(v0); v1 = gelu_f(v1); v2 = gelu_f(v2); v3 = gelu_f(v3); }
            if (MODE == 1) {
                float2 r0v = *(const float2*)(res + (size_t)r * N + col);
                float2 r1v = *(const float2*)(res + (size_t)(r + 8) * N + col);
                v0 += r0v.x; v1 += r0v.y; v2 += r1v.x; v3 += r1v.y;
                *(float2*)(C + (size_t)r * N + col)       = make_float2(v0, v1);
                *(float2*)(C + (size_t)(r + 8) * N + col) = make_float2(v2, v3);
            } else {
                store_split2(Ohi, Olo, (size_t)r * N + col,       v0, v1);
                store_split2(Ohi, Olo, (size_t)(r + 8) * N + col, v2, v3);
            }
        }
    }
}

// ================= tensor-core flash attention (bf16 split, causal) =============
// Q tile 64 (4 warps x m16), K/V tiles 64, hi/lo planes, cp.async double buffer.
// Reads packed qkv split (row stride QKVS); writes ctx split (row stride DD).
#define AP   72
#define APB  (AP * 2)          // 144 B row pitch
#define SPL  (64 * APB)        // plane bytes 9216
#define ATT_STAGE (4 * SPL)
#define ATT_SMEM  (2 * SPL + 2 * ATT_STAGE)   // 92160

__global__ void __launch_bounds__(128, 2) attn_mma(
    const __nv_bfloat16* __restrict__ Phi, const __nv_bfloat16* __restrict__ Plo,
    __nv_bfloat16* __restrict__ Ohi, __nv_bfloat16* __restrict__ Olo)
{
    extern __shared__ char smem[];
    const uint32_t sb = smem_to_u32(smem);
    const int tid = threadIdx.x, lane = tid & 31, wid = tid >> 5;
    const int qt = blockIdx.x, bh = blockIdx.y;
    const int b = bh >> 4, h = bh & 15;
    const int q0 = qt * 64, wm = wid * 16;
    const size_t gbase = (size_t)b * SS * QKVS + (size_t)h * HD;
    const __nv_bfloat16* srcH = Phi + gbase;
    const __nv_bfloat16* srcL = Plo + gbase;

    auto load_plane = [&](uint32_t dst, const __nv_bfloat16* src, int row0) {
        #pragma unroll
        for (int t = 0; t < 4; t++) {
            const int idx = tid + 128 * t;
            const int r = idx >> 3, c8 = (idx & 7) * 8;
            CP_ASYNC16(dst + (uint32_t)(r * APB + c8 * 2),
                       src + (size_t)(row0 + r) * QKVS + c8);
        }
    };
    auto load_kv = [&](int kt, int buf) {
        const uint32_t st = sb + 2 * SPL + buf * ATT_STAGE;
        const int k0r = kt * 64;
        load_plane(st,           srcH + 1024, k0r);   // K hi
        load_plane(st + SPL,     srcL + 1024, k0r);   // K lo
        load_plane(st + 2 * SPL, srcH + 2048, k0r);   // V hi
        load_plane(st + 3 * SPL, srcL + 2048, k0r);   // V lo
    };

    load_plane(sb,       srcH, q0);   // Q hi
    load_plane(sb + SPL, srcL, q0);   // Q lo
    load_kv(0, 0);
    CP_COMMIT();
    CP_WAIT(0);
    __syncthreads();

    // Q A-frags (m16k16 x 4 ksteps, hi+lo)
    uint32_t qh[4][4], ql[4][4];
    {
        const uint32_t qa = sb + (uint32_t)((wm + (lane & 15)) * APB + ((lane >> 4) * 8) * 2);
        #pragma unroll
        for (int ks = 0; ks < 4; ks++) {
            ldmx4(qh[ks], qa + (uint32_t)(ks * 16) * 2);
            ldmx4(ql[ks], qa + SPL + (uint32_t)(ks * 16) * 2);
        }
    }

    float oacc[8][4];
    #pragma unroll
    for (int j = 0; j < 8; j++)
        #pragma unroll
        for (int e = 0; e < 4; e++) oacc[j][e] = 0.f;
    float m0r = -1e30f, m1r = -1e30f, l0r = 0.f, l1r = 0.f;

    for (int kt = 0; kt <= qt; kt++) {
        const int buf = kt & 1;
        if (kt + 1 <= qt) { load_kv(kt + 1, buf ^ 1); CP_COMMIT(); CP_WAIT(1); }
        else CP_WAIT(0);
        __syncthreads();

        const uint32_t stK_h = sb + 2 * SPL + buf * ATT_STAGE;
        const uint32_t stK_l = stK_h + SPL;
        const uint32_t stV_h = stK_h + 2 * SPL;
        const uint32_t stV_l = stK_h + 3 * SPL;

        // ---- S = Q K^T (3-term split) ----
        float sacc[8][4];
        #pragma unroll
        for (int j = 0; j < 8; j++)
            #pragma unroll
            for (int e = 0; e < 4; e++) sacc[j][e] = 0.f;

        const uint32_t kba = (uint32_t)((lane & 7) * APB + (((lane >> 3) & 1) * 8) * 2);
        #pragma unroll
        for (int ks = 0; ks < 4; ks++) {
            uint32_t kh[8][2], kl[8][2];
            #pragma unroll
            for (int jn = 0; jn < 8; jn++) {
                const uint32_t a = kba + (uint32_t)(jn * 8 * APB) + (uint32_t)(ks * 16) * 2;
                ldmx2(kh[jn], stK_h + a);
                ldmx2(kl[jn], stK_l + a);
            }
            #pragma unroll
            for (int jn = 0; jn < 8; jn++) {
                mma16816(sacc[jn], qh[ks], kh[jn]);
                mma16816(sacc[jn], qh[ks], kl[jn]);
                mma16816(sacc[jn], ql[ks], kh[jn]);
            }
        }

        // ---- scale + causal mask + online softmax ----
        const int r0 = q0 + wm + (lane >> 2);
        const int k0 = kt * 64;
        const bool diag = (kt == qt);
        float mt0 = -1e30f, mt1 = -1e30f;
        #pragma unroll
        for (int jn = 0; jn < 8; jn++) {
            const int c0 = k0 + jn * 8 + (lane & 3) * 2;
            float v0 = sacc[jn][0] * 0.125f, v1 = sacc[jn][1] * 0.125f;
            float v2 = sacc[jn][2] * 0.125f, v3 = sacc[jn][3] * 0.125f;
            if (diag) {
                if (c0     > r0)     v0 = -1e30f;
                if (c0 + 1 > r0)     v1 = -1e30f;
                if (c0     > r0 + 8) v2 = -1e30f;
                if (c0 + 1 > r0 + 8) v3 = -1e30f;
            }
            sacc[jn][0] = v0; sacc[jn][1] = v1; sacc[jn][2] = v2; sacc[jn][3] = v3;
            mt0 = fmaxf(mt0, fmaxf(v0, v1));
            mt1 = fmaxf(mt1, fmaxf(v2, v3));
        }
        mt0 = fmaxf(mt0, __shfl_xor_sync(0xffffffffu, mt0, 1));
        mt0 = fmaxf(mt0, __shfl_xor_sync(0xffffffffu, mt0, 2));
        mt1 = fmaxf(mt1, __shfl_xor_sync(0xffffffffu, mt1, 1));
        mt1 = fmaxf(mt1, __shfl_xor_sync(0xffffffffu, mt1, 2));
        const float mn0 = fmaxf(m0r, mt0), mn1 = fmaxf(m1r, mt1);
        const float a0 = __expf(m0r - mn0), a1 = __expf(m1r - mn1);
        float ps0 = 0.f, ps1 = 0.f;
        #pragma unroll
        for (int jn = 0; jn < 8; jn++) {
            float p0 = __expf(sacc[jn][0] - mn0), p1 = __expf(sacc[jn][1] - mn0);
            float p2 = __expf(sacc[jn][2] - mn1), p3 = __expf(sacc[jn][3] - mn1);
            sacc[jn][0] = p0; sacc[jn][1] = p1; sacc[jn][2] = p2; sacc[jn][3] = p3;
            ps0 += p0 + p1; ps1 += p2 + p3;
        }
        ps0 += __shfl_xor_sync(0xffffffffu, ps0, 1);
        ps0 += __shfl_xor_sync(0xffffffffu, ps0, 2);
        ps1 += __shfl_xor_sync(0xffffffffu, ps1, 1);
        ps1 += __shfl_xor_sync(0xffffffffu, ps1, 2);
        l0r = l0r * a0 + ps0;  l1r = l1r * a1 + ps1;
        m0r = mn0;             m1r = mn1;
        #pragma unroll
        for (int jd = 0; jd < 8; jd++) {
            oacc[jd][0] *= a0; oacc[jd][1] *= a0;
            oacc[jd][2] *= a1; oacc[jd][3] *= a1;
        }

        // ---- O += P V (P split in-register, V via ldmatrix.trans) ----
        #pragma unroll
        for (int ks = 0; ks < 4; ks++) {
            uint32_t ah[4], al[4];
            split2(sacc[2*ks][0],     sacc[2*ks][1],     ah[0], al[0]);
            split2(sacc[2*ks][2],     sacc[2*ks][3],     ah[1], al[1]);
            split2(sacc[2*ks+1][0],   sacc[2*ks+1][1],   ah[2], al[2]);
            split2(sacc[2*ks+1][2],   sacc[2*ks+1][3],   ah[3], al[3]);
            const uint32_t vba = (uint32_t)((ks * 16 + (lane & 15)) * APB);
            #pragma unroll
            for (int jd = 0; jd < 8; jd++) {
                uint32_t vh[2], vl[2];
                ldmx2t(vh, stV_h + vba + (uint32_t)(jd * 8) * 2);
                ldmx2t(vl, stV_l + vba + (uint32_t)(jd * 8) * 2);
                mma16816(oacc[jd], ah, vh);
                mma16816(oacc[jd], ah, vl);
                mma16816(oacc[jd], al, vh);
            }
        }
        __syncthreads();
    }

    // ---- epilogue: normalize, split-store ctx ----
    const float i0 = 1.f / l0r, i1 = 1.f / l1r;
    const size_t obase = (size_t)b * SS * DD + (size_t)h * HD;
    const int orow = q0 + wm + (lane >> 2);
    #pragma unroll
    for (int jd = 0; jd < 8; jd++) {
        const int col = jd * 8 + (lane & 3) * 2;
        store_split2(Ohi, Olo, obase + (size_t)orow * DD + col,
                     oacc[jd][0] * i0, oacc[jd][1] * i0);
        store_split2(Ohi, Olo, obase + (size_t)(orow + 8) * DD + col,
                     oacc[jd][2] * i1, oacc[jd][3] * i1);
    }
}

// ---------------- launch ----------------
extern "C" void kernel_launch(void* const* d_in, const int* in_sizes, int n_in,
                              void* d_out, int out_size)
{
    const float* x    = (const float*)d_in[0];
    const float* Wq   = (const float*)d_in[1];
    const float* Wk   = (const float*)d_in[2];
    const float* Wv   = (const float*)d_in[3];
    const float* Wo   = (const float*)d_in[4];
    const float* bo   = (const float*)d_in[5];
    const float* W1   = (const float*)d_in[6];
    const float* b1   = (const float*)d_in[7];
    const float* W2   = (const float*)d_in[8];
    const float* b2   = (const float*)d_in[9];
    const float* ln1s = (const float*)d_in[10];
    const float* ln1b = (const float*)d_in[11];
    const float* ln2s = (const float*)d_in[12];
    const float* ln2b = (const float*)d_in[13];
    float* out = (float*)d_out;

    float *x2;
    __nv_bfloat16 *ahi, *alo, *bhi, *blo, *whi, *wlo;
    cudaGetSymbolAddress((void**)&x2,  g_x2);
    cudaGetSymbolAddress((void**)&ahi, g_ahi);
    cudaGetSymbolAddress((void**)&alo, g_alo);
    cudaGetSymbolAddress((void**)&bhi, g_bhi);
    cudaGetSymbolAddress((void**)&blo, g_blo);
    cudaGetSymbolAddress((void**)&whi, g_whi);
    cudaGetSymbolAddress((void**)&wlo, g_wlo);

    cudaFuncSetAttribute(attn_mma,   cudaFuncAttributeMaxDynamicSharedMemorySize, ATT_SMEM);
    cudaFuncSetAttribute(mm_gemm<0>, cudaFuncAttributeMaxDynamicSharedMemorySize, MM_SMEM);
    cudaFuncSetAttribute(mm_gemm<1>, cudaFuncAttributeMaxDynamicSharedMemorySize, MM_SMEM);
    cudaFuncSetAttribute(mm_gemm<2>, cudaFuncAttributeMaxDynamicSharedMemorySize, MM_SMEM);

    const dim3 gQKV(QKVS / 128, ROWS / 128);
    const dim3 gD(DD / 128, ROWS / 128);
    const dim3 gF(DFF / 128, ROWS / 128);
    const dim3 tWd(DD / 32, DD / 32);
    const dim3 tW1(DFF / 32, DD / 32);
    const dim3 tW2(DD / 32, DFF / 32);

    // 1) LN1 + split
    ln_split<<<ROWS, 256>>>(x, ln1s, ln1b, ahi, alo);

    // 2) fused QKV GEMM -> split qkv (bhi/blo, stride 3072)
    wt_split_T<<<tWd, 256>>>(Wq, whi,                   wlo,                   DD, DD);
    wt_split_T<<<tWd, 256>>>(Wk, whi + 1024*(size_t)DD, wlo + 1024*(size_t)DD, DD, DD);
    wt_split_T<<<tWd, 256>>>(Wv, whi + 2048*(size_t)DD, wlo + 2048*(size_t)DD, DD, DD);
    mm_gemm<0><<<gQKV, 256, MM_SMEM>>>(ahi, alo, whi, wlo, nullptr, nullptr,
                                       nullptr, bhi, blo, QKVS, DD);

    // 3) tensor-core flash attention -> ctx split (ahi/alo, stride 1024)
    dim3 gA(SS / 64, BB * HH);
    attn_mma<<<gA, 128, ATT_SMEM>>>(bhi, blo, ahi, alo);

    // 4) Wo + bias + residual -> x2 (fp32)
    wt_split_T<<<tWd, 256>>>(Wo, whi, wlo, DD, DD);
    mm_gemm<1><<<gD, 256, MM_SMEM>>>(ahi, alo, whi, wlo, bo, x, x2, nullptr, nullptr, DD, DD);

    // 5) LN2 + split
    ln_split<<<ROWS, 256>>>(x2, ln2s, ln2b, ahi, alo);

    // 6) FFN up + gelu -> split ffn (bhi/blo, stride 4096)
    wt_split_T<<<tW1, 256>>>(W1, whi, wlo, DD, DFF);
    mm_gemm<2><<<gF, 256, MM_SMEM>>>(ahi, alo, whi, wlo, b1, nullptr,
                                     nullptr, bhi, blo, DFF, DD);

    // 7) FFN down + bias + residual -> out (fp32)
    wt_split_T<<<tW2, 256>>>(W2, whi, wlo, DFF, DD);
    mm_gemm<1><<<gD, 256, MM_SMEM>>>(bhi, blo, whi, wlo, b2, x2, out, nullptr, nullptr, DD, DFF);
}